// round 4
// baseline (speedup 1.0000x reference)
#include <cuda_runtime.h>
#include <cuda_bf16.h>

// GINConv forward: out = segment_sum(X[ci]) @ W  ==  segment_sum((X@W)[ci])
// Kernel 1: Y = X @ W        (64-row tiles, pre-packed f32x2 operands)
// Kernel 2: out = segsum(Y[ci])  (half-warp/node, shuffle-distributed indices,
//                                 16 independent float4 gathers in flight)

#define D_FEAT 64
#define N_NODES_MAX 100000

// Scratch for Y (25.6 MB). __device__ global: allowed (no dynamic alloc).
__device__ __align__(16) float g_Y[(size_t)N_NODES_MAX * D_FEAT];

// ---- packed f32x2 helpers (sm_103a) ----
__device__ __forceinline__ unsigned long long pk2(float lo, float hi) {
    unsigned long long r;
    asm("mov.b64 %0, {%1, %2};" : "=l"(r) : "f"(lo), "f"(hi));
    return r;
}
__device__ __forceinline__ void unpk2(unsigned long long v, float& lo, float& hi) {
    asm("mov.b64 {%0, %1}, %2;" : "=f"(lo), "=f"(hi) : "l"(v));
}
__device__ __forceinline__ void fma2(unsigned long long& d,
                                     unsigned long long a,
                                     unsigned long long b) {
    asm("fma.rn.f32x2 %0, %1, %2, %0;" : "+l"(d) : "l"(a), "l"(b));
}

// ================= Kernel 1: Y = X @ W =================
// 64-row tile per block, 256 threads as 16x16, each thread a 4x4 micro-tile.
// Both operands pre-packed in smem as 64-bit f32x2 words:
//   Wp[k][p]  = (W[k][2p], W[k][2p+1])
//   Xp[r][k]  = (X[r][k], X[r][k])   (broadcast-duplicated)
// Inner loop per k: 1 LDS.128 (W) + 4 LDS.64 (X bcast) + 8 fma.rn.f32x2.
__global__ __launch_bounds__(256) void gemm_xw_kernel(
    const float* __restrict__ X,
    const float* __restrict__ W,
    float* __restrict__ Y,
    int n_rows)
{
    __shared__ __align__(16) unsigned long long Wp[D_FEAT * 32];   // 16 KB
    __shared__ __align__(16) unsigned long long Xp[D_FEAT][66];    // 33 KB padded

    const int tid = threadIdx.x;
    const int ty = tid >> 4;       // 0..15: row group (4 rows)
    const int tx = tid & 15;       // 0..15: col-pair group (4 cols)
    const int base = blockIdx.x * 64;

    // Stage W packed as column pairs
    #pragma unroll
    for (int i = tid; i < 1024; i += 256) {
        const float4 w4 = reinterpret_cast<const float4*>(W)[i];
        const int k = i >> 4, p = i & 15;
        Wp[k * 32 + 2 * p + 0] = pk2(w4.x, w4.y);
        Wp[k * 32 + 2 * p + 1] = pk2(w4.z, w4.w);
    }
    // Stage X tile, duplicated-packed (coalesced float4 global reads)
    #pragma unroll
    for (int i = tid; i < 1024; i += 256) {
        const int r = i >> 4, q = i & 15;
        float4 v = make_float4(0.f, 0.f, 0.f, 0.f);
        if (base + r < n_rows)
            v = reinterpret_cast<const float4*>(X)[(size_t)(base + r) * 16 + q];
        Xp[r][4 * q + 0] = pk2(v.x, v.x);
        Xp[r][4 * q + 1] = pk2(v.y, v.y);
        Xp[r][4 * q + 2] = pk2(v.z, v.z);
        Xp[r][4 * q + 3] = pk2(v.w, v.w);
    }
    __syncthreads();

    unsigned long long acc[4][2] = {};   // 4 rows x 2 col-pairs

    #pragma unroll 8
    for (int k = 0; k < D_FEAT; ++k) {
        const longlong2 w2 =
            reinterpret_cast<const longlong2*>(Wp + k * 32)[tx];   // LDS.128
        #pragma unroll
        for (int j = 0; j < 4; ++j) {
            const unsigned long long xx = Xp[ty * 4 + j][k];       // LDS.64 bcast
            fma2(acc[j][0], xx, (unsigned long long)w2.x);
            fma2(acc[j][1], xx, (unsigned long long)w2.y);
        }
    }

    #pragma unroll
    for (int j = 0; j < 4; ++j) {
        const int row = base + ty * 4 + j;
        if (row < n_rows) {
            float a, b, c, d;
            unpk2(acc[j][0], a, b);
            unpk2(acc[j][1], c, d);
            reinterpret_cast<float4*>(Y)[(size_t)row * 16 + tx] =
                make_float4(a, b, c, d);
        }
    }
}

// ============ Kernel 2: out = segment_sum(Y[ci]) ============
// Half-warp (16 lanes) per node; lane fl owns float4 chunk fl of the row.
// Fast path: 16-edge chunks. One coalesced ci load (lane fl -> ci[e+fl]),
// width-16 shuffles distribute indices, 16 independent LDG.128 gathers.
__global__ __launch_bounds__(256, 4) void gather_sum_kernel(
    const float4* __restrict__ Y4,
    const int* __restrict__ rp,
    const int* __restrict__ ci,
    float4* __restrict__ out4,
    int n_nodes)
{
    const int tid  = threadIdx.x;
    const int half = tid >> 4;
    const int fl   = tid & 15;
    const int node = blockIdx.x * 16 + half;
    if (node >= n_nodes) return;

    const unsigned hm = 0xFFFFu << (tid & 16);   // this half-warp's lane mask

    const int start = __ldg(&rp[node]);
    const int end   = __ldg(&rp[node + 1]);

    float4 a0 = make_float4(0.f, 0.f, 0.f, 0.f);
    float4 a1 = a0, a2 = a0, a3 = a0;

    int e = start;
    const int full_end = start + ((end - start) & ~15);

    // Fast path: full chunks of 16 edges
    for (; e < full_end; e += 16) {
        const int idx = __ldg(&ci[e + fl]);      // coalesced 64B per half-warp
        #pragma unroll
        for (int j = 0; j < 16; ++j) {
            const int c = __shfl_sync(hm, idx, j, 16);
            const float4 v = __ldg(&Y4[(size_t)c * 16 + fl]);
            float4& a = (j & 2) ? ((j & 1) ? a3 : a2) : ((j & 1) ? a1 : a0);
            a.x += v.x; a.y += v.y; a.z += v.z; a.w += v.w;
        }
    }

    // Tail: < 16 edges, 4-way broadcast loads
    for (; e + 4 <= end; e += 4) {
        const int c0 = __ldg(&ci[e + 0]);
        const int c1 = __ldg(&ci[e + 1]);
        const int c2 = __ldg(&ci[e + 2]);
        const int c3 = __ldg(&ci[e + 3]);
        const float4 v0 = __ldg(&Y4[(size_t)c0 * 16 + fl]);
        const float4 v1 = __ldg(&Y4[(size_t)c1 * 16 + fl]);
        const float4 v2 = __ldg(&Y4[(size_t)c2 * 16 + fl]);
        const float4 v3 = __ldg(&Y4[(size_t)c3 * 16 + fl]);
        a0.x += v0.x; a0.y += v0.y; a0.z += v0.z; a0.w += v0.w;
        a1.x += v1.x; a1.y += v1.y; a1.z += v1.z; a1.w += v1.w;
        a2.x += v2.x; a2.y += v2.y; a2.z += v2.z; a2.w += v2.w;
        a3.x += v3.x; a3.y += v3.y; a3.z += v3.z; a3.w += v3.w;
    }
    for (; e < end; ++e) {
        const int c = __ldg(&ci[e]);
        const float4 v = __ldg(&Y4[(size_t)c * 16 + fl]);
        a0.x += v.x; a0.y += v.y; a0.z += v.z; a0.w += v.w;
    }

    float4 r;
    r.x = (a0.x + a1.x) + (a2.x + a3.x);
    r.y = (a0.y + a1.y) + (a2.y + a3.y);
    r.z = (a0.z + a1.z) + (a2.z + a3.z);
    r.w = (a0.w + a1.w) + (a2.w + a3.w);

    out4[(size_t)node * 16 + fl] = r;   // warp = 2 consecutive rows: coalesced
}

extern "C" void kernel_launch(void* const* d_in, const int* in_sizes, int n_in,
                              void* d_out, int out_size) {
    const float* X  = (const float*)d_in[0];   // [100000, 64]
    const float* W  = (const float*)d_in[1];   // [64, 64]
    const int*   rp = (const int*)d_in[2];     // [100001]
    const int*   ci = (const int*)d_in[3];     // [1600000]
    float* out = (float*)d_out;                // [100000, 64]

    const int n_nodes = in_sizes[2] - 1;       // 100000

    float* Yptr = nullptr;
    cudaGetSymbolAddress((void**)&Yptr, g_Y);

    const int blocks1 = (n_nodes + 63) / 64;
    gemm_xw_kernel<<<blocks1, 256>>>(X, W, Yptr, n_nodes);

    const int blocks2 = (n_nodes + 15) / 16;
    gather_sum_kernel<<<blocks2, 256>>>(
        reinterpret_cast<const float4*>(Yptr), rp, ci,
        reinterpret_cast<float4*>(out), n_nodes);
}

// round 5
// speedup vs baseline: 1.3997x; 1.3997x over previous
#include <cuda_runtime.h>
#include <cuda_bf16.h>

// GINConv forward: out = segment_sum(X[ci]) @ W  ==  segment_sum((X@W)[ci])
// Kernel 1: Y = X @ W   (tiled 64x64, f32x2 packed FMA)  [R3 version]
// Kernel 2: out = segment_sum(Y[ci])  (half-warp per node, float4 gathers,
//           128-thread blocks for fine-grained scheduling / occupancy)

#define D_FEAT 64
#define N_NODES_MAX 100000

// Scratch for Y (25.6 MB). __device__ global: allowed (no dynamic alloc).
__device__ __align__(16) float g_Y[(size_t)N_NODES_MAX * D_FEAT];

// ---- packed f32x2 helpers (sm_103a) ----
__device__ __forceinline__ unsigned long long pk2(float lo, float hi) {
    unsigned long long r;
    asm("mov.b64 %0, {%1, %2};" : "=l"(r) : "f"(lo), "f"(hi));
    return r;
}
__device__ __forceinline__ void unpk2(unsigned long long v, float& lo, float& hi) {
    asm("mov.b64 {%0, %1}, %2;" : "=f"(lo), "=f"(hi) : "l"(v));
}
__device__ __forceinline__ void fma2(unsigned long long& d,
                                     unsigned long long a,
                                     unsigned long long b) {
    asm("fma.rn.f32x2 %0, %1, %2, %0;" : "+l"(d) : "l"(a), "l"(b));
}

// ================= Kernel 1: Y = X @ W =================
// 64-row tile per block, 256 threads as 16x16, each thread a 4x4 micro-tile.
__global__ __launch_bounds__(256) void gemm_xw_kernel(
    const float* __restrict__ X,
    const float* __restrict__ W,
    float* __restrict__ Y,
    int n_rows)
{
    __shared__ __align__(16) float Xs[D_FEAT][68];               // 17.4 KB
    __shared__ __align__(16) unsigned long long Wp[D_FEAT * 32]; // 16 KB

    const int tid = threadIdx.x;
    const int ty = tid >> 4;       // 0..15: row group
    const int tx = tid & 15;       // 0..15: col group
    const int base = blockIdx.x * 64;

    // Stage W packed as (col2p, col2p+1) pairs
    #pragma unroll
    for (int i = tid; i < 1024; i += 256) {
        const float4 w4 = reinterpret_cast<const float4*>(W)[i];
        const int k = i >> 4, p = i & 15;
        Wp[k * 32 + 2 * p + 0] = pk2(w4.x, w4.y);
        Wp[k * 32 + 2 * p + 1] = pk2(w4.z, w4.w);
    }
    // Stage X tile (coalesced float4)
    #pragma unroll
    for (int i = tid; i < 1024; i += 256) {
        const int r = i >> 4, q = i & 15;
        float4 v = make_float4(0.f, 0.f, 0.f, 0.f);
        if (base + r < n_rows)
            v = reinterpret_cast<const float4*>(X)[(size_t)(base + r) * 16 + q];
        *reinterpret_cast<float4*>(&Xs[r][q * 4]) = v;
    }
    __syncthreads();

    unsigned long long acc[4][2] = {};   // 4 rows x 4 cols (2 packed pairs)

    #pragma unroll 4
    for (int k = 0; k < D_FEAT; ++k) {
        const longlong2 w2 =
            reinterpret_cast<const longlong2*>(Wp + k * 32)[tx];  // LDS.128
        #pragma unroll
        for (int j = 0; j < 4; ++j) {
            const float x = Xs[ty * 4 + j][k];
            const unsigned long long xx = pk2(x, x);
            fma2(acc[j][0], xx, (unsigned long long)w2.x);
            fma2(acc[j][1], xx, (unsigned long long)w2.y);
        }
    }

    #pragma unroll
    for (int j = 0; j < 4; ++j) {
        const int row = base + ty * 4 + j;
        if (row < n_rows) {
            float a, b, c, d;
            unpk2(acc[j][0], a, b);
            unpk2(acc[j][1], c, d);
            reinterpret_cast<float4*>(Y)[(size_t)row * 16 + tx] =
                make_float4(a, b, c, d);
        }
    }
}

// ============ Kernel 2: out = segment_sum(Y[ci]) ============
// Half-warp (16 lanes) per node; each lane owns one float4 feature chunk.
// 4-way unrolled independent accumulators. 128-thread blocks, up to 12
// blocks/SM -> 48 warps theoretical, fine-grained retirement under degree
// imbalance.
__global__ __launch_bounds__(128, 12) void gather_sum_kernel(
    const float4* __restrict__ Y4,
    const int* __restrict__ rp,
    const int* __restrict__ ci,
    float4* __restrict__ out4,
    int n_nodes)
{
    const int tid  = threadIdx.x;
    const int half = tid >> 4;     // half-warp id within block: 0..7
    const int fl   = tid & 15;     // float4 index within the 64-float row
    const int node = blockIdx.x * 8 + half;
    if (node >= n_nodes) return;

    const int start = __ldg(&rp[node]);
    const int end   = __ldg(&rp[node + 1]);

    float4 a0 = make_float4(0.f, 0.f, 0.f, 0.f);
    float4 a1 = a0, a2 = a0, a3 = a0;

    int e = start;
    for (; e + 4 <= end; e += 4) {
        const int c0 = __ldg(&ci[e + 0]);
        const int c1 = __ldg(&ci[e + 1]);
        const int c2 = __ldg(&ci[e + 2]);
        const int c3 = __ldg(&ci[e + 3]);
        const float4 v0 = __ldg(&Y4[(size_t)c0 * 16 + fl]);
        const float4 v1 = __ldg(&Y4[(size_t)c1 * 16 + fl]);
        const float4 v2 = __ldg(&Y4[(size_t)c2 * 16 + fl]);
        const float4 v3 = __ldg(&Y4[(size_t)c3 * 16 + fl]);
        a0.x += v0.x; a0.y += v0.y; a0.z += v0.z; a0.w += v0.w;
        a1.x += v1.x; a1.y += v1.y; a1.z += v1.z; a1.w += v1.w;
        a2.x += v2.x; a2.y += v2.y; a2.z += v2.z; a2.w += v2.w;
        a3.x += v3.x; a3.y += v3.y; a3.z += v3.z; a3.w += v3.w;
    }
    for (; e < end; ++e) {
        const int c = __ldg(&ci[e]);
        const float4 v = __ldg(&Y4[(size_t)c * 16 + fl]);
        a0.x += v.x; a0.y += v.y; a0.z += v.z; a0.w += v.w;
    }

    float4 r;
    r.x = (a0.x + a1.x) + (a2.x + a3.x);
    r.y = (a0.y + a1.y) + (a2.y + a3.y);
    r.z = (a0.z + a1.z) + (a2.z + a3.z);
    r.w = (a0.w + a1.w) + (a2.w + a3.w);

    out4[(size_t)node * 16 + fl] = r;   // warp = 2 consecutive rows: coalesced
}

extern "C" void kernel_launch(void* const* d_in, const int* in_sizes, int n_in,
                              void* d_out, int out_size) {
    const float* X  = (const float*)d_in[0];   // [100000, 64]
    const float* W  = (const float*)d_in[1];   // [64, 64]
    const int*   rp = (const int*)d_in[2];     // [100001]
    const int*   ci = (const int*)d_in[3];     // [1600000]
    float* out = (float*)d_out;                // [100000, 64]

    const int n_nodes = in_sizes[2] - 1;       // 100000

    float* Yptr = nullptr;
    cudaGetSymbolAddress((void**)&Yptr, g_Y);

    const int blocks1 = (n_nodes + 63) / 64;
    gemm_xw_kernel<<<blocks1, 256>>>(X, W, Yptr, n_nodes);

    const int blocks2 = (n_nodes + 7) / 8;
    gather_sum_kernel<<<blocks2, 128>>>(
        reinterpret_cast<const float4*>(Yptr), rp, ci,
        reinterpret_cast<float4*>(out), n_nodes);
}